// round 11
// baseline (speedup 1.0000x reference)
#include <cuda_runtime.h>
#include <cuda_fp16.h>
#include <math.h>
#include <cstdint>

#define BATCH 4
#define SEQ   2048
#define DM    1024
#define NH    64
#define NSP   4      // key splits per q-tile

// ---------------- scratch (no cudaMalloc allowed) ----------------
__device__ __half g_q[BATCH * SEQ * NH];    // fp16, pre-scaled by 0.125
__device__ __half g_k[BATCH * SEQ * NH];    // fp16
__device__ __half g_vt[BATCH * NH * SEQ];   // fp16 transposed [h][s]
__device__ __half g_wt[192 * DM];           // W^T (q|k|v rows), fp16
__device__ float  g_po[BATCH * NSP * SEQ * NH];  // partial O (unnormalized)
__device__ float  g_pm[BATCH * NSP * SEQ];       // partial row max
__device__ float  g_pl[BATCH * NSP * SEQ];       // partial row sum

// mma.sync m16n8k16 fp16 (sm_80+ PTX; tensor pipe)
__device__ __forceinline__ void mma_f16(float d[4], const uint32_t a[4],
                                        uint32_t b0, uint32_t b1) {
    asm volatile(
        "mma.sync.aligned.m16n8k16.row.col.f32.f16.f16.f32 "
        "{%0,%1,%2,%3}, {%4,%5,%6,%7}, {%8,%9}, {%0,%1,%2,%3};\n"
        : "+f"(d[0]), "+f"(d[1]), "+f"(d[2]), "+f"(d[3])
        : "r"(a[0]), "r"(a[1]), "r"(a[2]), "r"(a[3]), "r"(b0), "r"(b1));
}

__device__ __forceinline__ uint2 c4h(float4 v) {
    __half2 a = __floats2half2_rn(v.x, v.y);
    __half2 b = __floats2half2_rn(v.z, v.w);
    uint2 r;
    r.x = *(uint32_t*)&a;
    r.y = *(uint32_t*)&b;
    return r;
}

// =================================================================
// Kernel 0: transpose W (q|k|v) -> g_wt[192][1024] fp16.
// =================================================================
__global__ __launch_bounds__(256) void wt_kernel(
    const float* __restrict__ Wq,
    const float* __restrict__ Wk,
    const float* __restrict__ Wv)
{
    __shared__ float t[64][65];
    const int tid = threadIdx.x;
    const int k0  = blockIdx.x * 64;
    const int y   = blockIdx.y;
    const float* W = (y == 0) ? Wq : (y == 1) ? Wk : Wv;

    #pragma unroll
    for (int i = 0; i < 16; i++) {
        const int idx = tid + i * 256;
        const int kk = idx >> 6, nn = idx & 63;
        t[kk][nn] = W[(k0 + kk) * NH + nn];
    }
    __syncthreads();
    #pragma unroll
    for (int i = 0; i < 16; i++) {
        const int idx = tid + i * 256;
        const int nn = idx >> 6, kk = idx & 63;
        g_wt[(y * 64 + nn) * DM + k0 + kk] = __float2half(t[kk][nn]);
    }
}

// =================================================================
// Kernel 1: QKV projection, fp16 m16n8k16.
// Grid (128, 3): m-block x weight group (q/k/v). Block M=64 x N=64,
// 8 warps (4x2), warp tile m16 x n32. Double-buffered smem,
// 2-deep LDG prefetch, 1 barrier/chunk. v group stores transposed
// into g_vt directly (vt kernel eliminated).
// =================================================================
#define QST 40

__global__ __launch_bounds__(256) void qkv_mma_kernel(
    const float* __restrict__ x,
    const float* __restrict__ bq,
    const float* __restrict__ bk,
    const float* __restrict__ bv)
{
    __shared__ __half As[2][64][QST];
    __shared__ __half Bs[2][64][QST];
    __shared__ float bias_sm[64];

    const int tid  = threadIdx.x;
    const int wid  = tid >> 5;
    const int lane = tid & 31;
    const int m0   = blockIdx.x * 64;
    const int y    = blockIdx.y;          // 0=q, 1=k, 2=v
    const int wm   = wid >> 1;            // 0..3 -> rows wm*16
    const int wn   = wid & 1;             // 0..1 -> cols wn*32
    const int gid  = lane >> 2;
    const int tig  = lane & 3;

    if (tid < 64) {
        const float* bias = (y == 0) ? bq : (y == 1) ? bk : bv;
        bias_sm[tid] = bias[tid];
    }

    float d[4][4];
    #pragma unroll
    for (int j = 0; j < 4; j++)
        #pragma unroll
        for (int c = 0; c < 4; c++) d[j][c] = 0.f;

    // x load: idx = tid + 256i (i<2): row = idx>>3, seg = idx&7 (4 f32)
    // W load: idx = tid (256): row = idx>>2, seg = idx&3 (8 halfs)
    float4 rx[2][2];
    uint4  rw[2];
    const __half* Wg = g_wt + (size_t)(y * 64) * DM;

    auto ldg_chunk = [&](int c, int slot) {
        const int kc = c * 32;
        #pragma unroll
        for (int i = 0; i < 2; i++) {
            const int idx = tid + 256 * i;
            rx[slot][i] = *(const float4*)&x[(size_t)(m0 + (idx >> 3)) * DM + kc + (idx & 7) * 4];
        }
        rw[slot] = *(const uint4*)&Wg[(size_t)(tid >> 2) * DM + kc + (tid & 3) * 8];
    };
    auto commit_chunk = [&](int slot, int buf) {
        #pragma unroll
        for (int i = 0; i < 2; i++) {
            const int idx = tid + 256 * i;
            *(uint2*)&As[buf][idx >> 3][(idx & 7) * 4] = c4h(rx[slot][i]);
        }
        *(uint4*)&Bs[buf][tid >> 2][(tid & 3) * 8] = rw[slot];
    };

    const int NC = DM / 32;  // 32 chunks
    ldg_chunk(0, 0);
    ldg_chunk(1, 1);
    commit_chunk(0, 0);
    ldg_chunk(2, 0);
    __syncthreads();

    for (int it = 0; it < NC; it++) {
        const int buf = it & 1;
        #pragma unroll
        for (int ks = 0; ks < 2; ks++) {
            const int k0 = ks * 16;
            uint32_t a[4];
            const int r = wm * 16 + gid;
            a[0] = *(const uint32_t*)&As[buf][r][k0 + 2 * tig];
            a[1] = *(const uint32_t*)&As[buf][r + 8][k0 + 2 * tig];
            a[2] = *(const uint32_t*)&As[buf][r][k0 + 2 * tig + 8];
            a[3] = *(const uint32_t*)&As[buf][r + 8][k0 + 2 * tig + 8];
            #pragma unroll
            for (int nt = 0; nt < 4; nt++) {
                const int n = wn * 32 + nt * 8 + gid;
                const uint32_t b0 = *(const uint32_t*)&Bs[buf][n][k0 + 2 * tig];
                const uint32_t b1 = *(const uint32_t*)&Bs[buf][n][k0 + 2 * tig + 8];
                mma_f16(d[nt], a, b0, b1);
            }
        }
        if (it + 1 < NC) commit_chunk((it + 1) & 1, (it + 1) & 1);
        if (it + 3 < NC) ldg_chunk(it + 3, (it + 1) & 1);
        __syncthreads();
    }

    // epilogue
    const int row = m0 + wm * 16 + gid;   // global row (row+8 is second)
    if (y < 2) {
        __half* dst = (y == 0) ? g_q : g_k;
        const float scale = (y == 0) ? 0.125f : 1.0f;
        #pragma unroll
        for (int nt = 0; nt < 4; nt++) {
            const int h0 = wn * 32 + nt * 8 + 2 * tig;
            const float b0 = bias_sm[h0];
            const float b1 = bias_sm[h0 + 1];
            __half2 w0 = __floats2half2_rn((d[nt][0] + b0) * scale,
                                           (d[nt][1] + b1) * scale);
            __half2 w1 = __floats2half2_rn((d[nt][2] + b0) * scale,
                                           (d[nt][3] + b1) * scale);
            *(uint32_t*)&dst[(size_t)row * NH + h0]       = *(uint32_t*)&w0;
            *(uint32_t*)&dst[(size_t)(row + 8) * NH + h0] = *(uint32_t*)&w1;
        }
    } else {
        // v: store transposed into g_vt[b][h][s]
        const int bb = m0 >> 11;              // block fully inside one batch
        const int s  = (m0 & 2047) + wm * 16 + gid;
        __half* dst = g_vt + (size_t)bb * NH * SEQ;
        #pragma unroll
        for (int nt = 0; nt < 4; nt++) {
            const int h0 = wn * 32 + nt * 8 + 2 * tig;
            const float b0 = bias_sm[h0];
            const float b1 = bias_sm[h0 + 1];
            dst[(size_t)h0 * SEQ + s]           = __float2half_rn(d[nt][0] + b0);
            dst[(size_t)(h0 + 1) * SEQ + s]     = __float2half_rn(d[nt][1] + b1);
            dst[(size_t)h0 * SEQ + s + 8]       = __float2half_rn(d[nt][2] + b0);
            dst[(size_t)(h0 + 1) * SEQ + s + 8] = __float2half_rn(d[nt][3] + b1);
        }
    }
}

// =================================================================
// Kernel 2: split-K causal flash attention (fp16 m16n8k16).
// Grid (64 qtiles, NSP splits, BATCH). 64 threads (2 warps), BQ=32.
// =================================================================
#define AST 72

__global__ __launch_bounds__(64) void attn_split_kernel()
{
    __shared__ __half ks[2][64][AST];
    __shared__ __half vs[2][64][AST];

    const int tid = threadIdx.x;
    const int qt  = 63 - blockIdx.x;      // heavy blocks first
    const int sp  = blockIdx.y;
    const int b   = blockIdx.z;
    const int q0  = qt * 32;
    const int nk  = (qt >> 1) + 1;
    const int ts  = (nk + NSP - 1) / NSP;
    const int tb  = sp * ts;
    const int te  = (tb + ts < nk) ? (tb + ts) : nk;

    float* PO = g_po + ((size_t)(b * NSP + sp) * SEQ + q0) * NH;
    float* PM = g_pm + (size_t)(b * NSP + sp) * SEQ + q0;
    float* PL = g_pl + (size_t)(b * NSP + sp) * SEQ + q0;

    if (tb >= nk) {
        #pragma unroll
        for (int i = 0; i < 4; i++) {
            const int idx = tid + 64 * i;
            const int row = idx >> 3, cg = (idx & 7) * 8;
            float4 z = make_float4(0.f, 0.f, 0.f, 0.f);
            *(float4*)&PO[(size_t)row * NH + cg]     = z;
            *(float4*)&PO[(size_t)row * NH + cg + 4] = z;
        }
        if (tid < 32) { PM[tid] = -1e30f; PL[tid] = 0.f; }
        return;
    }

    const __half* Q  = g_q  + (size_t)b * SEQ * NH;
    const __half* K  = g_k  + (size_t)b * SEQ * NH;
    const __half* VT = g_vt + (size_t)b * NH * SEQ;

    const int wid  = tid >> 5;
    const int lane = tid & 31;
    const int gid  = lane >> 2;
    const int tig  = lane & 3;
    const int r0   = wid * 16 + gid;
    const int r1   = r0 + 8;

    uint32_t qa[4][4];
    #pragma unroll
    for (int kc = 0; kc < 4; kc++) {
        const __half* p0 = &Q[(size_t)(q0 + r0) * NH + kc * 16 + 2 * tig];
        const __half* p1 = &Q[(size_t)(q0 + r1) * NH + kc * 16 + 2 * tig];
        qa[kc][0] = *(const uint32_t*)p0;
        qa[kc][1] = *(const uint32_t*)p1;
        qa[kc][2] = *(const uint32_t*)(p0 + 8);
        qa[kc][3] = *(const uint32_t*)(p1 + 8);
    }

    {
        const int kb = tb * 64;
        #pragma unroll
        for (int i = 0; i < 8; i++) {
            const int idx = tid + 64 * i;
            const int row = idx >> 3, seg = (idx & 7) * 8;
            *(uint4*)&ks[tb & 1][row][seg] =
                *(const uint4*)&K[(size_t)(kb + row) * NH + seg];
            *(uint4*)&vs[tb & 1][row][seg] =
                *(const uint4*)&VT[(size_t)row * SEQ + kb + seg];
        }
    }
    __syncthreads();

    float m0 = -1e30f, m1 = -1e30f, l0 = 0.f, l1 = 0.f;
    float d_o[8][4];
    #pragma unroll
    for (int nt = 0; nt < 8; nt++)
        #pragma unroll
        for (int c = 0; c < 4; c++) d_o[nt][c] = 0.f;

    for (int t = tb; t < te; t++) {
        if (t + 1 < te) {
            const int kb = (t + 1) * 64;
            const int bn = (t + 1) & 1;
            #pragma unroll
            for (int i = 0; i < 8; i++) {
                const int idx = tid + 64 * i;
                const int row = idx >> 3, seg = (idx & 7) * 8;
                *(uint4*)&ks[bn][row][seg] =
                    *(const uint4*)&K[(size_t)(kb + row) * NH + seg];
                *(uint4*)&vs[bn][row][seg] =
                    *(const uint4*)&VT[(size_t)row * SEQ + kb + seg];
            }
        }

        float sd[8][4];
        #pragma unroll
        for (int nt = 0; nt < 8; nt++)
            #pragma unroll
            for (int c = 0; c < 4; c++) sd[nt][c] = 0.f;
        {
            const __half (*kt)[AST] = ks[t & 1];
            #pragma unroll
            for (int kc = 0; kc < 4; kc++) {
                #pragma unroll
                for (int nt = 0; nt < 8; nt++) {
                    const __half* kp = &kt[8 * nt + gid][kc * 16 + 2 * tig];
                    mma_f16(sd[nt], qa[kc],
                            *(const uint32_t*)kp, *(const uint32_t*)(kp + 8));
                }
            }
        }

        if (t == nk - 1) {
            #pragma unroll
            for (int nt = 0; nt < 8; nt++) {
                const int kg = t * 64 + 8 * nt + 2 * tig;
                if (kg     > q0 + r0) sd[nt][0] = -1e30f;
                if (kg + 1 > q0 + r0) sd[nt][1] = -1e30f;
                if (kg     > q0 + r1) sd[nt][2] = -1e30f;
                if (kg + 1 > q0 + r1) sd[nt][3] = -1e30f;
            }
        }

        float t0 = -1e30f, t1 = -1e30f;
        #pragma unroll
        for (int nt = 0; nt < 8; nt++) {
            t0 = fmaxf(t0, fmaxf(sd[nt][0], sd[nt][1]));
            t1 = fmaxf(t1, fmaxf(sd[nt][2], sd[nt][3]));
        }
        t0 = fmaxf(t0, __shfl_xor_sync(0xffffffffu, t0, 1));
        t0 = fmaxf(t0, __shfl_xor_sync(0xffffffffu, t0, 2));
        t1 = fmaxf(t1, __shfl_xor_sync(0xffffffffu, t1, 1));
        t1 = fmaxf(t1, __shfl_xor_sync(0xffffffffu, t1, 2));
        const float mn0 = fmaxf(m0, t0);
        const float mn1 = fmaxf(m1, t1);
        const float f0 = __expf(m0 - mn0);
        const float f1 = __expf(m1 - mn1);
        m0 = mn0; m1 = mn1;
        #pragma unroll
        for (int nt = 0; nt < 8; nt++) {
            d_o[nt][0] *= f0; d_o[nt][1] *= f0;
            d_o[nt][2] *= f1; d_o[nt][3] *= f1;
        }

        uint32_t pa[4][4];
        float s0 = 0.f, s1 = 0.f;
        #pragma unroll
        for (int nt = 0; nt < 8; nt++) {
            __half2 h0 = __floats2half2_rn(__expf(sd[nt][0] - mn0),
                                           __expf(sd[nt][1] - mn0));
            __half2 h1 = __floats2half2_rn(__expf(sd[nt][2] - mn1),
                                           __expf(sd[nt][3] - mn1));
            float2 g0 = __half22float2(h0);
            float2 g1 = __half22float2(h1);
            s0 += g0.x + g0.y;
            s1 += g1.x + g1.y;
            const int kc = nt >> 1;
            if ((nt & 1) == 0) {
                pa[kc][0] = *(uint32_t*)&h0;
                pa[kc][1] = *(uint32_t*)&h1;
            } else {
                pa[kc][2] = *(uint32_t*)&h0;
                pa[kc][3] = *(uint32_t*)&h1;
            }
        }
        s0 += __shfl_xor_sync(0xffffffffu, s0, 1);
        s0 += __shfl_xor_sync(0xffffffffu, s0, 2);
        s1 += __shfl_xor_sync(0xffffffffu, s1, 1);
        s1 += __shfl_xor_sync(0xffffffffu, s1, 2);
        l0 = l0 * f0 + s0;
        l1 = l1 * f1 + s1;

        {
            const __half (*vt)[AST] = vs[t & 1];
            #pragma unroll
            for (int kc = 0; kc < 4; kc++) {
                #pragma unroll
                for (int nt = 0; nt < 8; nt++) {
                    const __half* vp = &vt[8 * nt + gid][kc * 16 + 2 * tig];
                    mma_f16(d_o[nt], pa[kc],
                            *(const uint32_t*)vp, *(const uint32_t*)(vp + 8));
                }
            }
        }
        __syncthreads();
    }

    if (tig == 0) {
        PM[r0] = m0; PL[r0] = l0;
        PM[r1] = m1; PL[r1] = l1;
    }
    #pragma unroll
    for (int nt = 0; nt < 8; nt++) {
        const int cc = 8 * nt + 2 * tig;
        *(float2*)&PO[(size_t)r0 * NH + cc] = make_float2(d_o[nt][0], d_o[nt][1]);
        *(float2*)&PO[(size_t)r1 * NH + cc] = make_float2(d_o[nt][2], d_o[nt][3]);
    }
}

// =================================================================
// Kernel 3: combine partials -> out.
// =================================================================
__global__ __launch_bounds__(256) void comb_kernel(float* __restrict__ out)
{
    const int tid = threadIdx.x;
    const int s   = blockIdx.x * 32 + (tid >> 3);
    const int b   = blockIdx.y;
    const int cg  = (tid & 7) * 8;

    float m[NSP], l[NSP];
    #pragma unroll
    for (int i = 0; i < NSP; i++) {
        m[i] = g_pm[(size_t)(b * NSP + i) * SEQ + s];
        l[i] = g_pl[(size_t)(b * NSP + i) * SEQ + s];
    }
    float M = m[0];
    #pragma unroll
    for (int i = 1; i < NSP; i++) M = fmaxf(M, m[i]);
    float w[NSP], L = 0.f;
    #pragma unroll
    for (int i = 0; i < NSP; i++) {
        w[i] = __expf(m[i] - M);
        L += w[i] * l[i];
    }
    const float inv = 1.f / L;

    float acc[8] = {0.f, 0.f, 0.f, 0.f, 0.f, 0.f, 0.f, 0.f};
    #pragma unroll
    for (int i = 0; i < NSP; i++) {
        const float* p = &g_po[((size_t)(b * NSP + i) * SEQ + s) * NH + cg];
        float4 o0 = *(const float4*)p;
        float4 o1 = *(const float4*)(p + 4);
        acc[0] += w[i] * o0.x; acc[1] += w[i] * o0.y;
        acc[2] += w[i] * o0.z; acc[3] += w[i] * o0.w;
        acc[4] += w[i] * o1.x; acc[5] += w[i] * o1.y;
        acc[6] += w[i] * o1.z; acc[7] += w[i] * o1.w;
    }
    float* dst = &out[(size_t)(b * SEQ + s) * NH + cg];
    *(float4*)dst       = make_float4(acc[0] * inv, acc[1] * inv,
                                      acc[2] * inv, acc[3] * inv);
    *(float4*)(dst + 4) = make_float4(acc[4] * inv, acc[5] * inv,
                                      acc[6] * inv, acc[7] * inv);
}

// =================================================================
// launch
// =================================================================
extern "C" void kernel_launch(void* const* d_in, const int* in_sizes, int n_in,
                              void* d_out, int out_size)
{
    (void)in_sizes; (void)n_in; (void)out_size;
    const float* x  = (const float*)d_in[0];
    const float* Wq = (const float*)d_in[1];
    const float* bq = (const float*)d_in[2];
    const float* Wk = (const float*)d_in[3];
    const float* bk = (const float*)d_in[4];
    const float* Wv = (const float*)d_in[5];
    const float* bv = (const float*)d_in[6];
    float* out = (float*)d_out;

    wt_kernel<<<dim3(16, 3), 256>>>(Wq, Wk, Wv);
    qkv_mma_kernel<<<dim3((BATCH * SEQ) / 64, 3), 256>>>(x, bq, bk, bv);
    attn_split_kernel<<<dim3(64, NSP, BATCH), 64>>>();
    comb_kernel<<<dim3(SEQ / 32, BATCH), 256>>>(out);
}